// round 1
// baseline (speedup 1.0000x reference)
#include <cuda_runtime.h>
#include <cuda_bf16.h>
#include <math.h>

// ---------------------------------------------------------------------------
// Problem constants
// ---------------------------------------------------------------------------
#define BATCH   4
#define SEQ     2048
#define DMODEL  1024
#define NHEAD   16
#define DK      64
#define DFF     4096
#define NTOK    (BATCH * SEQ)          // 8192
#define LN_EPS  1e-5f

// ---------------------------------------------------------------------------
// Scratch (device globals — allocation-free rule)
// ---------------------------------------------------------------------------
__device__ float g_q   [NTOK * DMODEL];
__device__ float g_k   [NTOK * DMODEL];
__device__ float g_v   [NTOK * DMODEL];
__device__ float g_ctx [NTOK * DMODEL];
__device__ float g_attn[NTOK * DMODEL];
__device__ float g_h   [NTOK * DMODEL];
__device__ float g_ff  [NTOK * DFF];
__device__ float g_f2  [NTOK * DMODEL];

// ---------------------------------------------------------------------------
// SGEMM: C[M,N] = A[M,K] @ B[K,N] (+bias) (+relu).  Row-major everything.
// 128x128 block tile, BK=16, 256 threads, 8x8 micro-tile.
// All dims here are multiples of the tiles -> no bounds checks.
// ---------------------------------------------------------------------------
template<bool BIAS, bool RELU>
__global__ __launch_bounds__(256)
void sgemm_kernel(const float* __restrict__ A, const float* __restrict__ B,
                  const float* __restrict__ bias, float* __restrict__ C,
                  int M, int N, int K) {
    constexpr int BM = 128, BN = 128, BK = 16;
    __shared__ float As[BM][BK + 1];   // [row][k], padded
    __shared__ float Bs[BK][BN];       // [k][col]

    const int tid = threadIdx.x;
    const int tx  = tid & 15;          // 0..15 -> col group
    const int ty  = tid >> 4;          // 0..15 -> row group
    const int rowBase = blockIdx.y * BM;
    const int colBase = blockIdx.x * BN;

    float acc[8][8];
#pragma unroll
    for (int i = 0; i < 8; i++)
#pragma unroll
        for (int j = 0; j < 8; j++) acc[i][j] = 0.f;

    const int arow = tid >> 2;          // 0..63
    const int acol = (tid & 3) * 4;     // 0,4,8,12
    const int brow = tid >> 5;          // 0..7
    const int bcol = (tid & 31) * 4;    // 0..124

    for (int kt = 0; kt < K; kt += BK) {
        // load A tile (128 x 16), two rows of 64 per pass
#pragma unroll
        for (int l = 0; l < 2; l++) {
            int r = arow + l * 64;
            float4 av = *(const float4*)(A + (size_t)(rowBase + r) * K + kt + acol);
            As[r][acol + 0] = av.x;
            As[r][acol + 1] = av.y;
            As[r][acol + 2] = av.z;
            As[r][acol + 3] = av.w;
        }
        // load B tile (16 x 128)
#pragma unroll
        for (int l = 0; l < 2; l++) {
            int r = brow + l * 8;
            *(float4*)&Bs[r][bcol] =
                *(const float4*)(B + (size_t)(kt + r) * N + colBase + bcol);
        }
        __syncthreads();

#pragma unroll
        for (int kk = 0; kk < BK; kk++) {
            float a[8], b[8];
#pragma unroll
            for (int i = 0; i < 8; i++) a[i] = As[ty * 8 + i][kk];
            float4 b0 = *(const float4*)&Bs[kk][tx * 8];
            float4 b1 = *(const float4*)&Bs[kk][tx * 8 + 4];
            b[0] = b0.x; b[1] = b0.y; b[2] = b0.z; b[3] = b0.w;
            b[4] = b1.x; b[5] = b1.y; b[6] = b1.z; b[7] = b1.w;
#pragma unroll
            for (int i = 0; i < 8; i++)
#pragma unroll
                for (int j = 0; j < 8; j++)
                    acc[i][j] = fmaf(a[i], b[j], acc[i][j]);
        }
        __syncthreads();
    }

    // epilogue
#pragma unroll
    for (int i = 0; i < 8; i++) {
        const size_t row = rowBase + ty * 8 + i;
#pragma unroll
        for (int j = 0; j < 8; j += 4) {
            int col = colBase + tx * 8 + j;
            float4 vv;
            vv.x = acc[i][j + 0];
            vv.y = acc[i][j + 1];
            vv.z = acc[i][j + 2];
            vv.w = acc[i][j + 3];
            if (BIAS) {
                vv.x += bias[col + 0];
                vv.y += bias[col + 1];
                vv.z += bias[col + 2];
                vv.w += bias[col + 3];
            }
            if (RELU) {
                vv.x = fmaxf(vv.x, 0.f);
                vv.y = fmaxf(vv.y, 0.f);
                vv.z = fmaxf(vv.z, 0.f);
                vv.w = fmaxf(vv.w, 0.f);
            }
            *(float4*)(C + row * N + col) = vv;
        }
    }
}

// ---------------------------------------------------------------------------
// Flash attention (fp32, online softmax).
// q/k/v/ctx layout: [token, DMODEL] where head h occupies cols [h*64, h*64+64).
// grid = (SEQ/BQ, NHEAD, BATCH), 128 threads.
// BQ = BK = 64, dk = 64. Thread (ty: 0..7, tx: 0..15) owns an 8x4 sub-tile.
// Dynamic smem: Qs,Ks,Vs,Ps each 64 x 65 floats (padded) = 66,560 B.
// ---------------------------------------------------------------------------
#define FA_BQ 64
#define FA_BK 64
#define FA_LD 65
#define FA_SMEM (4 * FA_BQ * FA_LD * sizeof(float))

__global__ __launch_bounds__(128)
void flash_attn_kernel(const float* __restrict__ q, const float* __restrict__ k,
                       const float* __restrict__ v, float* __restrict__ ctx) {
    extern __shared__ float sm[];
    float* Qs = sm;                         // [64][65]
    float* Ks = Qs + FA_BQ * FA_LD;
    float* Vs = Ks + FA_BK * FA_LD;
    float* Ps = Vs + FA_BK * FA_LD;

    const int tid = threadIdx.x;
    const int tx = tid & 15;                // 0..15 : 4 cols each
    const int ty = tid >> 4;                // 0..7  : 8 rows each
    const int qt = blockIdx.x;
    const int h  = blockIdx.y;
    const int b  = blockIdx.z;

    const size_t base = (size_t)b * SEQ * DMODEL + (size_t)h * DK;

    // load Q tile
    for (int e = tid; e < FA_BQ * DK; e += 128) {
        int r = e >> 6, d = e & 63;
        Qs[r * FA_LD + d] = q[base + (size_t)(qt * FA_BQ + r) * DMODEL + d];
    }

    float m[8], l[8], acc[8][4];
#pragma unroll
    for (int i = 0; i < 8; i++) {
        m[i] = -1e30f; l[i] = 0.f;
#pragma unroll
        for (int j = 0; j < 4; j++) acc[i][j] = 0.f;
    }
    __syncthreads();

    const float scale = 0.125f;   // 1/sqrt(64)

    for (int kt = 0; kt < SEQ / FA_BK; kt++) {
        // load K, V tiles
        for (int e = tid; e < FA_BK * DK; e += 128) {
            int r = e >> 6, d = e & 63;
            size_t g = base + (size_t)(kt * FA_BK + r) * DMODEL + d;
            Ks[r * FA_LD + d] = k[g];
            Vs[r * FA_LD + d] = v[g];
        }
        __syncthreads();

        // scores: s[i][j] = sum_d Q[ty*8+i][d] * K[tx*4+j][d]
        float s[8][4];
#pragma unroll
        for (int i = 0; i < 8; i++)
#pragma unroll
            for (int j = 0; j < 4; j++) s[i][j] = 0.f;

#pragma unroll 8
        for (int d = 0; d < DK; d++) {
            float qv[8], kv[4];
#pragma unroll
            for (int i = 0; i < 8; i++) qv[i] = Qs[(ty * 8 + i) * FA_LD + d];
#pragma unroll
            for (int j = 0; j < 4; j++) kv[j] = Ks[(tx * 4 + j) * FA_LD + d];
#pragma unroll
            for (int i = 0; i < 8; i++)
#pragma unroll
                for (int j = 0; j < 4; j++)
                    s[i][j] = fmaf(qv[i], kv[j], s[i][j]);
        }

        // online softmax per q-row (reduce across the 16 tx lanes)
#pragma unroll
        for (int i = 0; i < 8; i++) {
            float rm = -1e30f;
#pragma unroll
            for (int j = 0; j < 4; j++) {
                s[i][j] *= scale;
                rm = fmaxf(rm, s[i][j]);
            }
#pragma unroll
            for (int off = 8; off > 0; off >>= 1)
                rm = fmaxf(rm, __shfl_xor_sync(0xffffffffu, rm, off));

            float mnew = fmaxf(m[i], rm);
            float corr = __expf(m[i] - mnew);
            float rsum = 0.f;
#pragma unroll
            for (int j = 0; j < 4; j++) {
                float p = __expf(s[i][j] - mnew);
                Ps[(ty * 8 + i) * FA_LD + tx * 4 + j] = p;
                rsum += p;
            }
#pragma unroll
            for (int off = 8; off > 0; off >>= 1)
                rsum += __shfl_xor_sync(0xffffffffu, rsum, off);

            l[i] = l[i] * corr + rsum;
            m[i] = mnew;
#pragma unroll
            for (int j = 0; j < 4; j++) acc[i][j] *= corr;
        }
        __syncthreads();   // Ps visible to all

        // acc += P @ V   (output cols tx*4+j)
#pragma unroll 4
        for (int kk = 0; kk < FA_BK; kk++) {
            float pv[8], vv[4];
#pragma unroll
            for (int i = 0; i < 8; i++) pv[i] = Ps[(ty * 8 + i) * FA_LD + kk];
#pragma unroll
            for (int j = 0; j < 4; j++) vv[j] = Vs[kk * FA_LD + tx * 4 + j];
#pragma unroll
            for (int i = 0; i < 8; i++)
#pragma unroll
                for (int j = 0; j < 4; j++)
                    acc[i][j] = fmaf(pv[i], vv[j], acc[i][j]);
        }
        __syncthreads();   // done with Ks/Vs/Ps before next tile
    }

    // epilogue: ctx = acc / l
#pragma unroll
    for (int i = 0; i < 8; i++) {
        float inv = 1.0f / l[i];
        size_t row = base + (size_t)(qt * FA_BQ + ty * 8 + i) * DMODEL + tx * 4;
#pragma unroll
        for (int j = 0; j < 4; j++)
            ctx[row + j] = acc[i][j] * inv;
    }
}

// ---------------------------------------------------------------------------
// out = LayerNorm(a + b) * gamma + beta, row-wise over DMODEL=1024.
// One 256-thread block per row; each thread handles 4 columns.
// ---------------------------------------------------------------------------
__global__ __launch_bounds__(256)
void add_ln_kernel(const float* __restrict__ a, const float* __restrict__ b,
                   const float* __restrict__ gamma, const float* __restrict__ beta,
                   float* __restrict__ out) {
    const int row = blockIdx.x;
    const int tid = threadIdx.x;
    const size_t off = (size_t)row * DMODEL;

    __shared__ float r1[8], r2[8];

    float vals[4];
    float sum = 0.f, sq = 0.f;
#pragma unroll
    for (int t = 0; t < 4; t++) {
        int c = tid + t * 256;
        float vv = a[off + c] + b[off + c];
        vals[t] = vv;
        sum += vv;
        sq  += vv * vv;
    }
#pragma unroll
    for (int o = 16; o > 0; o >>= 1) {
        sum += __shfl_xor_sync(0xffffffffu, sum, o);
        sq  += __shfl_xor_sync(0xffffffffu, sq,  o);
    }
    const int wid = tid >> 5;
    if ((tid & 31) == 0) { r1[wid] = sum; r2[wid] = sq; }
    __syncthreads();
    float tot1 = 0.f, tot2 = 0.f;
#pragma unroll
    for (int w = 0; w < 8; w++) { tot1 += r1[w]; tot2 += r2[w]; }

    const float mu   = tot1 * (1.0f / DMODEL);
    const float var  = tot2 * (1.0f / DMODEL) - mu * mu;
    const float rstd = rsqrtf(var + LN_EPS);

#pragma unroll
    for (int t = 0; t < 4; t++) {
        int c = tid + t * 256;
        out[off + c] = (vals[t] - mu) * rstd * gamma[c] + beta[c];
    }
}

// ---------------------------------------------------------------------------
// Launcher
// ---------------------------------------------------------------------------
extern "C" void kernel_launch(void* const* d_in, const int* in_sizes, int n_in,
                              void* d_out, int out_size) {
    (void)in_sizes; (void)n_in; (void)out_size;
    const float* x   = (const float*)d_in[0];
    const float* wq  = (const float*)d_in[1];
    const float* wk  = (const float*)d_in[2];
    const float* wv  = (const float*)d_in[3];
    const float* wo  = (const float*)d_in[4];
    const float* w1  = (const float*)d_in[5];
    const float* b1  = (const float*)d_in[6];
    const float* w2  = (const float*)d_in[7];
    const float* b2  = (const float*)d_in[8];
    const float* g1  = (const float*)d_in[9];
    const float* be1 = (const float*)d_in[10];
    const float* g2  = (const float*)d_in[11];
    const float* be2 = (const float*)d_in[12];
    float* out = (float*)d_out;

    float *q, *k, *v, *ctx, *attn, *h, *ff, *f2;
    cudaGetSymbolAddress((void**)&q,    g_q);
    cudaGetSymbolAddress((void**)&k,    g_k);
    cudaGetSymbolAddress((void**)&v,    g_v);
    cudaGetSymbolAddress((void**)&ctx,  g_ctx);
    cudaGetSymbolAddress((void**)&attn, g_attn);
    cudaGetSymbolAddress((void**)&h,    g_h);
    cudaGetSymbolAddress((void**)&ff,   g_ff);
    cudaGetSymbolAddress((void**)&f2,   g_f2);

    const dim3 g_dd(DMODEL / 128, NTOK / 128);   // (8, 64)
    const dim3 g_df(DFF / 128,    NTOK / 128);   // (32, 64)

    // Q, K, V projections
    sgemm_kernel<false, false><<<g_dd, 256>>>(x, wq, nullptr, q, NTOK, DMODEL, DMODEL);
    sgemm_kernel<false, false><<<g_dd, 256>>>(x, wk, nullptr, k, NTOK, DMODEL, DMODEL);
    sgemm_kernel<false, false><<<g_dd, 256>>>(x, wv, nullptr, v, NTOK, DMODEL, DMODEL);

    // attention
    cudaFuncSetAttribute(flash_attn_kernel,
                         cudaFuncAttributeMaxDynamicSharedMemorySize, FA_SMEM);
    flash_attn_kernel<<<dim3(SEQ / FA_BQ, NHEAD, BATCH), 128, FA_SMEM>>>(q, k, v, ctx);

    // output projection
    sgemm_kernel<false, false><<<g_dd, 256>>>(ctx, wo, nullptr, attn, NTOK, DMODEL, DMODEL);

    // add & norm 1
    add_ln_kernel<<<NTOK, 256>>>(x, attn, g1, be1, h);

    // FFN
    sgemm_kernel<true, true ><<<g_df, 256>>>(h,  w1, b1, ff, NTOK, DFF,    DMODEL);
    sgemm_kernel<true, false><<<g_dd, 256>>>(ff, w2, b2, f2, NTOK, DMODEL, DFF);

    // add & norm 2
    add_ln_kernel<<<NTOK, 256>>>(h, f2, g2, be2, out);
}

// round 2
// speedup vs baseline: 2.4231x; 2.4231x over previous
#include <cuda_runtime.h>
#include <cuda_bf16.h>
#include <math.h>
#include <stdint.h>

// ---------------------------------------------------------------------------
// Problem constants
// ---------------------------------------------------------------------------
#define BATCH   4
#define SEQ     2048
#define DMODEL  1024
#define NHEAD   16
#define DK      64
#define DFF     4096
#define NTOK    (BATCH * SEQ)          // 8192
#define LN_EPS  1e-5f

// ---------------------------------------------------------------------------
// Scratch (device globals — allocation-free rule)
// ---------------------------------------------------------------------------
__device__ float g_q   [NTOK * DMODEL];
__device__ float g_k   [NTOK * DMODEL];
__device__ float g_v   [NTOK * DMODEL];
__device__ float g_ctx [NTOK * DMODEL];
__device__ float g_attn[NTOK * DMODEL];
__device__ float g_h   [NTOK * DMODEL];
__device__ float g_ff  [NTOK * DFF];
__device__ float g_f2  [NTOK * DMODEL];

// ---------------------------------------------------------------------------
// TF32 helpers
// ---------------------------------------------------------------------------
__device__ __forceinline__ float to_tf32(float x) {
    asm("cvt.rna.tf32.f32 %0, %1;" : "=f"(x) : "f"(x));
    return x;
}
__device__ __forceinline__ float4 to_tf32x4(float4 v) {
    v.x = to_tf32(v.x); v.y = to_tf32(v.y);
    v.z = to_tf32(v.z); v.w = to_tf32(v.w);
    return v;
}

// mma.m16n8k8 row.col f32 += tf32 * tf32
__device__ __forceinline__ void mma_tf32(float* c, const uint32_t* a, const uint32_t* b) {
    asm volatile(
        "mma.sync.aligned.m16n8k8.row.col.f32.tf32.tf32.f32 "
        "{%0,%1,%2,%3}, {%4,%5,%6,%7}, {%8,%9}, {%0,%1,%2,%3};"
        : "+f"(c[0]), "+f"(c[1]), "+f"(c[2]), "+f"(c[3])
        : "r"(a[0]), "r"(a[1]), "r"(a[2]), "r"(a[3]), "r"(b[0]), "r"(b[1]));
}

// ---------------------------------------------------------------------------
// TF32 tensor-core GEMM: C[M,N] = A[M,K] @ B[K,N] (+bias) (+relu). Row-major.
// 128x128 block tile, BK=32, 256 threads (8 warps), warp tile 64x32.
// All dims are multiples of the tiles -> no bounds checks.
// ---------------------------------------------------------------------------
#define GA_LD 40    // As stride (32 + 8)
#define GB_LD 132   // Bs stride (128 + 4)

template<bool BIAS, bool RELU>
__global__ __launch_bounds__(256, 2)
void tf32_gemm(const float* __restrict__ A, const float* __restrict__ B,
               const float* __restrict__ bias, float* __restrict__ C,
               int M, int N, int K) {
    constexpr int BM = 128, BN = 128, BK = 32;
    __shared__ float As[BM][GA_LD];   // [m][k]
    __shared__ float Bs[BK][GB_LD];   // [k][n]

    const int tid  = threadIdx.x;
    const int lane = tid & 31;
    const int warp = tid >> 5;
    const int wm   = warp & 1;        // 0..1 -> 64-row half
    const int wn   = warp >> 1;       // 0..3 -> 32-col quarter
    const int g    = lane >> 2;       // groupID 0..7
    const int th   = lane & 3;        // 0..3

    const int rowBase = blockIdx.y * BM;
    const int colBase = blockIdx.x * BN;

    float acc[4][4][4];               // [mt][nt][reg]
#pragma unroll
    for (int i = 0; i < 4; i++)
#pragma unroll
        for (int j = 0; j < 4; j++)
#pragma unroll
            for (int r = 0; r < 4; r++) acc[i][j][r] = 0.f;

    const int arow = tid >> 3;          // 0..31
    const int acol = (tid & 7) * 4;     // 0..28
    const int bcol = (tid & 31) * 4;    // 0..124
    const int brow = tid >> 5;          // 0..7

    for (int kt = 0; kt < K; kt += BK) {
        // A tile: 128 x 32
#pragma unroll
        for (int p = 0; p < 4; p++) {
            int r = arow + p * 32;
            float4 v = *(const float4*)(A + (size_t)(rowBase + r) * K + kt + acol);
            *(float4*)&As[r][acol] = to_tf32x4(v);
        }
        // B tile: 32 x 128
#pragma unroll
        for (int p = 0; p < 4; p++) {
            int r = brow + p * 8;
            float4 v = *(const float4*)(B + (size_t)(kt + r) * N + colBase + bcol);
            *(float4*)&Bs[r][bcol] = to_tf32x4(v);
        }
        __syncthreads();

#pragma unroll
        for (int ks = 0; ks < 4; ks++) {
            const int k0 = ks * 8;
            uint32_t af[4][4], bf[4][2];
#pragma unroll
            for (int mt = 0; mt < 4; mt++) {
                int r0 = wm * 64 + mt * 16 + g;
                af[mt][0] = __float_as_uint(As[r0    ][k0 + th    ]);
                af[mt][1] = __float_as_uint(As[r0 + 8][k0 + th    ]);
                af[mt][2] = __float_as_uint(As[r0    ][k0 + th + 4]);
                af[mt][3] = __float_as_uint(As[r0 + 8][k0 + th + 4]);
            }
#pragma unroll
            for (int nt = 0; nt < 4; nt++) {
                int c0 = wn * 32 + nt * 8 + g;
                bf[nt][0] = __float_as_uint(Bs[k0 + th    ][c0]);
                bf[nt][1] = __float_as_uint(Bs[k0 + th + 4][c0]);
            }
#pragma unroll
            for (int mt = 0; mt < 4; mt++)
#pragma unroll
                for (int nt = 0; nt < 4; nt++)
                    mma_tf32(acc[mt][nt], af[mt], bf[nt]);
        }
        __syncthreads();
    }

    // epilogue: c0,c1 -> [r][2th,2th+1]; c2,c3 -> [r+8][...]
#pragma unroll
    for (int mt = 0; mt < 4; mt++) {
        const int r0 = rowBase + wm * 64 + mt * 16 + g;
#pragma unroll
        for (int nt = 0; nt < 4; nt++) {
            const int c0 = colBase + wn * 32 + nt * 8 + 2 * th;
            float2 v0 = make_float2(acc[mt][nt][0], acc[mt][nt][1]);
            float2 v1 = make_float2(acc[mt][nt][2], acc[mt][nt][3]);
            if (BIAS) {
                float2 bb = *(const float2*)(bias + c0);
                v0.x += bb.x; v0.y += bb.y;
                v1.x += bb.x; v1.y += bb.y;
            }
            if (RELU) {
                v0.x = fmaxf(v0.x, 0.f); v0.y = fmaxf(v0.y, 0.f);
                v1.x = fmaxf(v1.x, 0.f); v1.y = fmaxf(v1.y, 0.f);
            }
            *(float2*)(C + (size_t)r0 * N + c0)       = v0;
            *(float2*)(C + (size_t)(r0 + 8) * N + c0) = v1;
        }
    }
}

// ---------------------------------------------------------------------------
// Flash attention with TF32 tensor cores.
// grid = (SEQ/64, NHEAD, BATCH), 128 threads (4 warps).
// Each warp owns 16 q-rows. Per kv-tile (64): S = Q@K^T (mma), online softmax
// (fp32, quad shuffles), P -> smem (tf32), O += P@V (mma).
// Dynamic smem: Qs,Ks,Vs,Ps each [64][72] floats = 73728 B.
// ---------------------------------------------------------------------------
#define AT_LD   72
#define AT_TILE (64 * AT_LD)
#define AT_SMEM (4 * AT_TILE * sizeof(float))

__global__ __launch_bounds__(128)
void flash_attn_tf32(const float* __restrict__ q, const float* __restrict__ k,
                     const float* __restrict__ v, float* __restrict__ ctx) {
    extern __shared__ float sm[];
    float* Qs = sm;
    float* Ks = Qs + AT_TILE;
    float* Vs = Ks + AT_TILE;
    float* Ps = Vs + AT_TILE;

    const int tid  = threadIdx.x;
    const int lane = tid & 31;
    const int warp = tid >> 5;        // 0..3 -> 16 q rows each
    const int g    = lane >> 2;
    const int th   = lane & 3;
    const int qt   = blockIdx.x;
    const int h    = blockIdx.y;
    const int b    = blockIdx.z;

    const size_t base = (size_t)b * SEQ * DMODEL + (size_t)h * DK;
    const float scale = 0.125f;       // 1/sqrt(64)

    // load Q tile (tf32-rounded)
    for (int e = tid; e < 64 * 64; e += 128) {
        int r = e >> 6, d = e & 63;
        Qs[r * AT_LD + d] = to_tf32(q[base + (size_t)(qt * 64 + r) * DMODEL + d]);
    }

    float m0 = -1e30f, m1 = -1e30f, l0 = 0.f, l1 = 0.f;
    float o[8][4];                    // 8 d-tiles x 4 regs
#pragma unroll
    for (int i = 0; i < 8; i++)
#pragma unroll
        for (int j = 0; j < 4; j++) o[i][j] = 0.f;

    const int qrow = warp * 16 + g;   // this thread's row pair: qrow, qrow+8

    for (int kt = 0; kt < SEQ / 64; kt++) {
        // load K, V tiles
        for (int e = tid; e < 64 * 64; e += 128) {
            int r = e >> 6, d = e & 63;
            size_t go = base + (size_t)(kt * 64 + r) * DMODEL + d;
            Ks[r * AT_LD + d] = to_tf32(k[go]);
            Vs[r * AT_LD + d] = to_tf32(v[go]);
        }
        __syncthreads();

        // ---- scores S = Q @ K^T : M=16 (q), N=64 (kv), K=64 (d) ----
        float s[8][4];
#pragma unroll
        for (int nt = 0; nt < 8; nt++)
#pragma unroll
            for (int r = 0; r < 4; r++) s[nt][r] = 0.f;

#pragma unroll
        for (int ks = 0; ks < 8; ks++) {
            const int k0 = ks * 8;
            uint32_t af[4];
            af[0] = __float_as_uint(Qs[qrow * AT_LD + k0 + th]);
            af[1] = __float_as_uint(Qs[(qrow + 8) * AT_LD + k0 + th]);
            af[2] = __float_as_uint(Qs[qrow * AT_LD + k0 + th + 4]);
            af[3] = __float_as_uint(Qs[(qrow + 8) * AT_LD + k0 + th + 4]);
#pragma unroll
            for (int nt = 0; nt < 8; nt++) {
                uint32_t bf[2];
                bf[0] = __float_as_uint(Ks[(nt * 8 + g) * AT_LD + k0 + th]);
                bf[1] = __float_as_uint(Ks[(nt * 8 + g) * AT_LD + k0 + th + 4]);
                mma_tf32(s[nt], af, bf);
            }
        }

        // ---- online softmax (rows qrow and qrow+8) ----
        float rm0 = -1e30f, rm1 = -1e30f;
#pragma unroll
        for (int nt = 0; nt < 8; nt++) {
            s[nt][0] *= scale; s[nt][1] *= scale;
            s[nt][2] *= scale; s[nt][3] *= scale;
            rm0 = fmaxf(rm0, fmaxf(s[nt][0], s[nt][1]));
            rm1 = fmaxf(rm1, fmaxf(s[nt][2], s[nt][3]));
        }
        rm0 = fmaxf(rm0, __shfl_xor_sync(0xffffffffu, rm0, 1));
        rm0 = fmaxf(rm0, __shfl_xor_sync(0xffffffffu, rm0, 2));
        rm1 = fmaxf(rm1, __shfl_xor_sync(0xffffffffu, rm1, 1));
        rm1 = fmaxf(rm1, __shfl_xor_sync(0xffffffffu, rm1, 2));

        const float mn0 = fmaxf(m0, rm0);
        const float mn1 = fmaxf(m1, rm1);
        const float corr0 = __expf(m0 - mn0);
        const float corr1 = __expf(m1 - mn1);

        float rs0 = 0.f, rs1 = 0.f;
#pragma unroll
        for (int nt = 0; nt < 8; nt++) {
            const int c0 = nt * 8 + 2 * th;
            float p00 = __expf(s[nt][0] - mn0);
            float p01 = __expf(s[nt][1] - mn0);
            float p10 = __expf(s[nt][2] - mn1);
            float p11 = __expf(s[nt][3] - mn1);
            rs0 += p00 + p01;
            rs1 += p10 + p11;
            Ps[qrow * AT_LD + c0]           = to_tf32(p00);
            Ps[qrow * AT_LD + c0 + 1]       = to_tf32(p01);
            Ps[(qrow + 8) * AT_LD + c0]     = to_tf32(p10);
            Ps[(qrow + 8) * AT_LD + c0 + 1] = to_tf32(p11);
        }
        rs0 += __shfl_xor_sync(0xffffffffu, rs0, 1);
        rs0 += __shfl_xor_sync(0xffffffffu, rs0, 2);
        rs1 += __shfl_xor_sync(0xffffffffu, rs1, 1);
        rs1 += __shfl_xor_sync(0xffffffffu, rs1, 2);

        l0 = l0 * corr0 + rs0;
        l1 = l1 * corr1 + rs1;
        m0 = mn0;
        m1 = mn1;

#pragma unroll
        for (int dt = 0; dt < 8; dt++) {
            o[dt][0] *= corr0; o[dt][1] *= corr0;
            o[dt][2] *= corr1; o[dt][3] *= corr1;
        }
        __syncwarp();   // Ps writes visible within the warp

        // ---- O += P @ V : M=16 (q), N=64 (d), K=64 (kv) ----
#pragma unroll
        for (int ks = 0; ks < 8; ks++) {
            const int k0 = ks * 8;
            uint32_t af[4];
            af[0] = __float_as_uint(Ps[qrow * AT_LD + k0 + th]);
            af[1] = __float_as_uint(Ps[(qrow + 8) * AT_LD + k0 + th]);
            af[2] = __float_as_uint(Ps[qrow * AT_LD + k0 + th + 4]);
            af[3] = __float_as_uint(Ps[(qrow + 8) * AT_LD + k0 + th + 4]);
#pragma unroll
            for (int dt = 0; dt < 8; dt++) {
                uint32_t bf[2];
                bf[0] = __float_as_uint(Vs[(k0 + th) * AT_LD + dt * 8 + g]);
                bf[1] = __float_as_uint(Vs[(k0 + th + 4) * AT_LD + dt * 8 + g]);
                mma_tf32(o[dt], af, bf);
            }
        }
        __syncthreads();   // done with Ks/Vs before next tile load
    }

    // epilogue
    const float inv0 = 1.0f / l0;
    const float inv1 = 1.0f / l1;
    const size_t row0 = base + (size_t)(qt * 64 + qrow) * DMODEL;
    const size_t row1 = base + (size_t)(qt * 64 + qrow + 8) * DMODEL;
#pragma unroll
    for (int dt = 0; dt < 8; dt++) {
        const int c0 = dt * 8 + 2 * th;
        *(float2*)(ctx + row0 + c0) = make_float2(o[dt][0] * inv0, o[dt][1] * inv0);
        *(float2*)(ctx + row1 + c0) = make_float2(o[dt][2] * inv1, o[dt][3] * inv1);
    }
}

// ---------------------------------------------------------------------------
// out = LayerNorm(a + b) * gamma + beta, row-wise over DMODEL=1024.
// ---------------------------------------------------------------------------
__global__ __launch_bounds__(256)
void add_ln_kernel(const float* __restrict__ a, const float* __restrict__ b,
                   const float* __restrict__ gamma, const float* __restrict__ beta,
                   float* __restrict__ out) {
    const int row = blockIdx.x;
    const int tid = threadIdx.x;
    const size_t off = (size_t)row * DMODEL;

    __shared__ float r1[8], r2[8];

    float vals[4];
    float sum = 0.f, sq = 0.f;
#pragma unroll
    for (int t = 0; t < 4; t++) {
        int c = tid + t * 256;
        float vv = a[off + c] + b[off + c];
        vals[t] = vv;
        sum += vv;
        sq  += vv * vv;
    }
#pragma unroll
    for (int o = 16; o > 0; o >>= 1) {
        sum += __shfl_xor_sync(0xffffffffu, sum, o);
        sq  += __shfl_xor_sync(0xffffffffu, sq,  o);
    }
    const int wid = tid >> 5;
    if ((tid & 31) == 0) { r1[wid] = sum; r2[wid] = sq; }
    __syncthreads();
    float tot1 = 0.f, tot2 = 0.f;
#pragma unroll
    for (int w = 0; w < 8; w++) { tot1 += r1[w]; tot2 += r2[w]; }

    const float mu   = tot1 * (1.0f / DMODEL);
    const float var  = tot2 * (1.0f / DMODEL) - mu * mu;
    const float rstd = rsqrtf(var + LN_EPS);

#pragma unroll
    for (int t = 0; t < 4; t++) {
        int c = tid + t * 256;
        out[off + c] = (vals[t] - mu) * rstd * gamma[c] + beta[c];
    }
}

// ---------------------------------------------------------------------------
// Launcher
// ---------------------------------------------------------------------------
extern "C" void kernel_launch(void* const* d_in, const int* in_sizes, int n_in,
                              void* d_out, int out_size) {
    (void)in_sizes; (void)n_in; (void)out_size;
    const float* x   = (const float*)d_in[0];
    const float* wq  = (const float*)d_in[1];
    const float* wk  = (const float*)d_in[2];
    const float* wv  = (const float*)d_in[3];
    const float* wo  = (const float*)d_in[4];
    const float* w1  = (const float*)d_in[5];
    const float* b1  = (const float*)d_in[6];
    const float* w2  = (const float*)d_in[7];
    const float* b2  = (const float*)d_in[8];
    const float* g1  = (const float*)d_in[9];
    const float* be1 = (const float*)d_in[10];
    const float* g2  = (const float*)d_in[11];
    const float* be2 = (const float*)d_in[12];
    float* out = (float*)d_out;

    float *q, *k, *v, *ctx, *attn, *h, *ff, *f2;
    cudaGetSymbolAddress((void**)&q,    g_q);
    cudaGetSymbolAddress((void**)&k,    g_k);
    cudaGetSymbolAddress((void**)&v,    g_v);
    cudaGetSymbolAddress((void**)&ctx,  g_ctx);
    cudaGetSymbolAddress((void**)&attn, g_attn);
    cudaGetSymbolAddress((void**)&h,    g_h);
    cudaGetSymbolAddress((void**)&ff,   g_ff);
    cudaGetSymbolAddress((void**)&f2,   g_f2);

    const dim3 g_dd(DMODEL / 128, NTOK / 128);   // (8, 64)
    const dim3 g_df(DFF / 128,    NTOK / 128);   // (32, 64)

    // Q, K, V projections
    tf32_gemm<false, false><<<g_dd, 256>>>(x, wq, nullptr, q, NTOK, DMODEL, DMODEL);
    tf32_gemm<false, false><<<g_dd, 256>>>(x, wk, nullptr, k, NTOK, DMODEL, DMODEL);
    tf32_gemm<false, false><<<g_dd, 256>>>(x, wv, nullptr, v, NTOK, DMODEL, DMODEL);

    // attention
    cudaFuncSetAttribute(flash_attn_tf32,
                         cudaFuncAttributeMaxDynamicSharedMemorySize, (int)AT_SMEM);
    flash_attn_tf32<<<dim3(SEQ / 64, NHEAD, BATCH), 128, AT_SMEM>>>(q, k, v, ctx);

    // output projection
    tf32_gemm<false, false><<<g_dd, 256>>>(ctx, wo, nullptr, attn, NTOK, DMODEL, DMODEL);

    // add & norm 1
    add_ln_kernel<<<NTOK, 256>>>(x, attn, g1, be1, h);

    // FFN
    tf32_gemm<true, true ><<<g_df, 256>>>(h,  w1, b1, ff, NTOK, DFF,    DMODEL);
    tf32_gemm<true, false><<<g_dd, 256>>>(ff, w2, b2, f2, NTOK, DMODEL, DFF);

    // add & norm 2
    add_ln_kernel<<<NTOK, 256>>>(h, f2, g2, be2, out);
}

// round 3
// speedup vs baseline: 3.0808x; 1.2715x over previous
#include <cuda_runtime.h>
#include <cuda_bf16.h>
#include <math.h>
#include <stdint.h>

// ---------------------------------------------------------------------------
// Problem constants
// ---------------------------------------------------------------------------
#define BATCH   4
#define SEQ     2048
#define DMODEL  1024
#define NHEAD   16
#define DK      64
#define DFF     4096
#define NTOK    (BATCH * SEQ)          // 8192
#define LN_EPS  1e-5f

// ---------------------------------------------------------------------------
// Scratch (device globals — allocation-free rule)
// ---------------------------------------------------------------------------
__device__ float g_q   [NTOK * DMODEL];
__device__ float g_k   [NTOK * DMODEL];
__device__ float g_v   [NTOK * DMODEL];
__device__ float g_ctx [NTOK * DMODEL];
__device__ float g_attn[NTOK * DMODEL];
__device__ float g_h   [NTOK * DMODEL];
__device__ float g_ff  [NTOK * DFF];
__device__ float g_f2  [NTOK * DMODEL];

// ---------------------------------------------------------------------------
// TF32 / async-copy helpers
// ---------------------------------------------------------------------------
__device__ __forceinline__ float to_tf32(float x) {
    asm("cvt.rna.tf32.f32 %0, %1;" : "=f"(x) : "f"(x));
    return x;
}

__device__ __forceinline__ uint32_t smem_u32(const void* p) {
    return (uint32_t)__cvta_generic_to_shared(p);
}
__device__ __forceinline__ void cp_async16(uint32_t dst, const void* src) {
    asm volatile("cp.async.cg.shared.global [%0], [%1], 16;\n" :: "r"(dst), "l"(src));
}
__device__ __forceinline__ void cp_commit() { asm volatile("cp.async.commit_group;\n"); }
__device__ __forceinline__ void cp_wait1()  { asm volatile("cp.async.wait_group 1;\n"); }
__device__ __forceinline__ void cp_wait0()  { asm volatile("cp.async.wait_group 0;\n"); }

// mma.m16n8k8 row.col f32 += tf32 * tf32
__device__ __forceinline__ void mma_tf32(float* c, const uint32_t* a, const uint32_t* b) {
    asm volatile(
        "mma.sync.aligned.m16n8k8.row.col.f32.tf32.tf32.f32 "
        "{%0,%1,%2,%3}, {%4,%5,%6,%7}, {%8,%9}, {%0,%1,%2,%3};"
        : "+f"(c[0]), "+f"(c[1]), "+f"(c[2]), "+f"(c[3])
        : "r"(a[0]), "r"(a[1]), "r"(a[2]), "r"(a[3]), "r"(b[0]), "r"(b[1]));
}

// ---------------------------------------------------------------------------
// TF32 tensor-core GEMM with 2-stage cp.async pipeline.
// C[M,N] = A[M,K] @ B[K,N] (+bias) (+relu). Row-major.
// 128x128 block tile, BK=32, 256 threads (8 warps), warp tile 64x32.
// Dynamic smem: 2 * (128*36 + 32*136) * 4 = 71,680 B.
// ---------------------------------------------------------------------------
#define GA_LD 36    // As stride: 36 % 32 == 4 -> A-frag bank = 4g+th (conflict-free)
#define GB_LD 136   // Bs stride: 136 % 32 == 8 -> B-frag bank = 8th+g (conflict-free)
#define GEMM_SMEM (2 * (128 * GA_LD + 32 * GB_LD) * (int)sizeof(float))

template<bool BIAS, bool RELU>
__global__ __launch_bounds__(256, 2)
void tf32_gemm(const float* __restrict__ A, const float* __restrict__ B,
               const float* __restrict__ bias, float* __restrict__ C,
               int M, int N, int K) {
    constexpr int BM = 128, BN = 128, BK = 32;
    extern __shared__ float gsm[];
    float (*As)[BM][GA_LD] = reinterpret_cast<float(*)[BM][GA_LD]>(gsm);
    float (*Bs)[BK][GB_LD] = reinterpret_cast<float(*)[BK][GB_LD]>(gsm + 2 * BM * GA_LD);

    const int tid  = threadIdx.x;
    const int lane = tid & 31;
    const int warp = tid >> 5;
    const int wm   = warp & 1;        // 0..1 -> 64-row half
    const int wn   = warp >> 1;       // 0..3 -> 32-col quarter
    const int g    = lane >> 2;       // 0..7
    const int th   = lane & 3;        // 0..3

    const int rowBase = blockIdx.y * BM;
    const int colBase = blockIdx.x * BN;

    const int arow = tid >> 3;          // 0..31
    const int acol = (tid & 7) * 4;     // 0..28
    const int brow = tid >> 5;          // 0..7
    const int bcol = (tid & 31) * 4;    // 0..124

    float acc[4][4][4];
#pragma unroll
    for (int i = 0; i < 4; i++)
#pragma unroll
        for (int j = 0; j < 4; j++)
#pragma unroll
            for (int r = 0; r < 4; r++) acc[i][j][r] = 0.f;

    auto load_tile = [&](int kt, int buf) {
#pragma unroll
        for (int p = 0; p < 4; p++) {
            int r = arow + p * 32;
            cp_async16(smem_u32(&As[buf][r][acol]),
                       A + (size_t)(rowBase + r) * K + kt + acol);
        }
#pragma unroll
        for (int p = 0; p < 4; p++) {
            int r = brow + p * 8;
            cp_async16(smem_u32(&Bs[buf][r][bcol]),
                       B + (size_t)(kt + r) * N + colBase + bcol);
        }
    };

    const int nk = K / BK;
    load_tile(0, 0);
    cp_commit();

    for (int it = 0; it < nk; it++) {
        const int buf = it & 1;
        if (it + 1 < nk) {
            load_tile((it + 1) * BK, buf ^ 1);
            cp_commit();
            cp_wait1();
        } else {
            cp_wait0();
        }
        __syncthreads();

#pragma unroll
        for (int ks = 0; ks < 4; ks++) {
            const int k0 = ks * 8;
            uint32_t af[4][4], bf[4][2];
#pragma unroll
            for (int mt = 0; mt < 4; mt++) {
                int r0 = wm * 64 + mt * 16 + g;
                af[mt][0] = __float_as_uint(to_tf32(As[buf][r0    ][k0 + th    ]));
                af[mt][1] = __float_as_uint(to_tf32(As[buf][r0 + 8][k0 + th    ]));
                af[mt][2] = __float_as_uint(to_tf32(As[buf][r0    ][k0 + th + 4]));
                af[mt][3] = __float_as_uint(to_tf32(As[buf][r0 + 8][k0 + th + 4]));
            }
#pragma unroll
            for (int nt = 0; nt < 4; nt++) {
                int c0 = wn * 32 + nt * 8 + g;
                bf[nt][0] = __float_as_uint(to_tf32(Bs[buf][k0 + th    ][c0]));
                bf[nt][1] = __float_as_uint(to_tf32(Bs[buf][k0 + th + 4][c0]));
            }
#pragma unroll
            for (int mt = 0; mt < 4; mt++)
#pragma unroll
                for (int nt = 0; nt < 4; nt++)
                    mma_tf32(acc[mt][nt], af[mt], bf[nt]);
        }
        __syncthreads();
    }

    // epilogue
#pragma unroll
    for (int mt = 0; mt < 4; mt++) {
        const int r0 = rowBase + wm * 64 + mt * 16 + g;
#pragma unroll
        for (int nt = 0; nt < 4; nt++) {
            const int c0 = colBase + wn * 32 + nt * 8 + 2 * th;
            float2 v0 = make_float2(acc[mt][nt][0], acc[mt][nt][1]);
            float2 v1 = make_float2(acc[mt][nt][2], acc[mt][nt][3]);
            if (BIAS) {
                float2 bb = *(const float2*)(bias + c0);
                v0.x += bb.x; v0.y += bb.y;
                v1.x += bb.x; v1.y += bb.y;
            }
            if (RELU) {
                v0.x = fmaxf(v0.x, 0.f); v0.y = fmaxf(v0.y, 0.f);
                v1.x = fmaxf(v1.x, 0.f); v1.y = fmaxf(v1.y, 0.f);
            }
            *(float2*)(C + (size_t)r0 * N + c0)       = v0;
            *(float2*)(C + (size_t)(r0 + 8) * N + c0) = v1;
        }
    }
}

// ---------------------------------------------------------------------------
// Flash attention with TF32 tensor cores.
// grid = (SEQ/64, NHEAD, BATCH), 128 threads (4 warps), 16 q-rows per warp.
// Q fragments live in registers for the whole kv loop (staged once via Ps).
// smem: Ks, Vs, Ps, each [64][72] floats = 55,296 B -> 4 CTAs/SM.
// ---------------------------------------------------------------------------
#define AT_LD   72
#define AT_TILE (64 * AT_LD)
#define AT_SMEM (3 * AT_TILE * (int)sizeof(float))

__global__ __launch_bounds__(128, 4)
void flash_attn_tf32(const float* __restrict__ q, const float* __restrict__ k,
                     const float* __restrict__ v, float* __restrict__ ctx) {
    extern __shared__ float sm[];
    float* Ks = sm;
    float* Vs = Ks + AT_TILE;
    float* Ps = Vs + AT_TILE;   // also used to stage Q once at start

    const int tid  = threadIdx.x;
    const int lane = tid & 31;
    const int warp = tid >> 5;        // 0..3 -> 16 q rows each
    const int g    = lane >> 2;
    const int th   = lane & 3;
    const int qt   = blockIdx.x;
    const int h    = blockIdx.y;
    const int b    = blockIdx.z;

    const size_t base = (size_t)b * SEQ * DMODEL + (size_t)h * DK;
    const float scale = 0.125f;       // 1/sqrt(64)
    const int qrow = warp * 16 + g;   // this thread's row pair: qrow, qrow+8

    // ---- stage Q tile once, pull fragments into registers ----
    for (int e = tid; e < 64 * 64; e += 128) {
        int r = e >> 6, d = e & 63;
        Ps[r * AT_LD + d] = to_tf32(q[base + (size_t)(qt * 64 + r) * DMODEL + d]);
    }
    __syncthreads();

    uint32_t qf[8][4];
#pragma unroll
    for (int ks = 0; ks < 8; ks++) {
        const int k0 = ks * 8;
        qf[ks][0] = __float_as_uint(Ps[qrow * AT_LD + k0 + th]);
        qf[ks][1] = __float_as_uint(Ps[(qrow + 8) * AT_LD + k0 + th]);
        qf[ks][2] = __float_as_uint(Ps[qrow * AT_LD + k0 + th + 4]);
        qf[ks][3] = __float_as_uint(Ps[(qrow + 8) * AT_LD + k0 + th + 4]);
    }
    __syncthreads();

    float m0 = -1e30f, m1 = -1e30f, l0 = 0.f, l1 = 0.f;
    float o[8][4];
#pragma unroll
    for (int i = 0; i < 8; i++)
#pragma unroll
        for (int j = 0; j < 4; j++) o[i][j] = 0.f;

    for (int kt = 0; kt < SEQ / 64; kt++) {
        // load K, V tiles (tf32-rounded)
        for (int e = tid; e < 64 * 64; e += 128) {
            int r = e >> 6, d = e & 63;
            size_t go = base + (size_t)(kt * 64 + r) * DMODEL + d;
            Ks[r * AT_LD + d] = to_tf32(k[go]);
            Vs[r * AT_LD + d] = to_tf32(v[go]);
        }
        __syncthreads();

        // ---- scores S = Q @ K^T : M=16, N=64 (kv), K=64 (d) ----
        float s[8][4];
#pragma unroll
        for (int nt = 0; nt < 8; nt++)
#pragma unroll
            for (int r = 0; r < 4; r++) s[nt][r] = 0.f;

#pragma unroll
        for (int ks = 0; ks < 8; ks++) {
            const int k0 = ks * 8;
#pragma unroll
            for (int nt = 0; nt < 8; nt++) {
                uint32_t bf[2];
                bf[0] = __float_as_uint(Ks[(nt * 8 + g) * AT_LD + k0 + th]);
                bf[1] = __float_as_uint(Ks[(nt * 8 + g) * AT_LD + k0 + th + 4]);
                mma_tf32(s[nt], qf[ks], bf);
            }
        }

        // ---- online softmax (rows qrow, qrow+8) ----
        float rm0 = -1e30f, rm1 = -1e30f;
#pragma unroll
        for (int nt = 0; nt < 8; nt++) {
            s[nt][0] *= scale; s[nt][1] *= scale;
            s[nt][2] *= scale; s[nt][3] *= scale;
            rm0 = fmaxf(rm0, fmaxf(s[nt][0], s[nt][1]));
            rm1 = fmaxf(rm1, fmaxf(s[nt][2], s[nt][3]));
        }
        rm0 = fmaxf(rm0, __shfl_xor_sync(0xffffffffu, rm0, 1));
        rm0 = fmaxf(rm0, __shfl_xor_sync(0xffffffffu, rm0, 2));
        rm1 = fmaxf(rm1, __shfl_xor_sync(0xffffffffu, rm1, 1));
        rm1 = fmaxf(rm1, __shfl_xor_sync(0xffffffffu, rm1, 2));

        const float mn0 = fmaxf(m0, rm0);
        const float mn1 = fmaxf(m1, rm1);
        const float corr0 = __expf(m0 - mn0);
        const float corr1 = __expf(m1 - mn1);

        float rs0 = 0.f, rs1 = 0.f;
#pragma unroll
        for (int nt = 0; nt < 8; nt++) {
            const int c0 = nt * 8 + 2 * th;
            float p00 = __expf(s[nt][0] - mn0);
            float p01 = __expf(s[nt][1] - mn0);
            float p10 = __expf(s[nt][2] - mn1);
            float p11 = __expf(s[nt][3] - mn1);
            rs0 += p00 + p01;
            rs1 += p10 + p11;
            Ps[qrow * AT_LD + c0]           = to_tf32(p00);
            Ps[qrow * AT_LD + c0 + 1]       = to_tf32(p01);
            Ps[(qrow + 8) * AT_LD + c0]     = to_tf32(p10);
            Ps[(qrow + 8) * AT_LD + c0 + 1] = to_tf32(p11);
        }
        rs0 += __shfl_xor_sync(0xffffffffu, rs0, 1);
        rs0 += __shfl_xor_sync(0xffffffffu, rs0, 2);
        rs1 += __shfl_xor_sync(0xffffffffu, rs1, 1);
        rs1 += __shfl_xor_sync(0xffffffffu, rs1, 2);

        l0 = l0 * corr0 + rs0;
        l1 = l1 * corr1 + rs1;
        m0 = mn0;
        m1 = mn1;

#pragma unroll
        for (int dt = 0; dt < 8; dt++) {
            o[dt][0] *= corr0; o[dt][1] *= corr0;
            o[dt][2] *= corr1; o[dt][3] *= corr1;
        }
        __syncwarp();   // Ps rows are warp-private; warp-level sync suffices

        // ---- O += P @ V : M=16, N=64 (d), K=64 (kv) ----
#pragma unroll
        for (int ks = 0; ks < 8; ks++) {
            const int k0 = ks * 8;
            uint32_t af[4];
            af[0] = __float_as_uint(Ps[qrow * AT_LD + k0 + th]);
            af[1] = __float_as_uint(Ps[(qrow + 8) * AT_LD + k0 + th]);
            af[2] = __float_as_uint(Ps[qrow * AT_LD + k0 + th + 4]);
            af[3] = __float_as_uint(Ps[(qrow + 8) * AT_LD + k0 + th + 4]);
#pragma unroll
            for (int dt = 0; dt < 8; dt++) {
                uint32_t bf[2];
                bf[0] = __float_as_uint(Vs[(k0 + th) * AT_LD + dt * 8 + g]);
                bf[1] = __float_as_uint(Vs[(k0 + th + 4) * AT_LD + dt * 8 + g]);
                mma_tf32(o[dt], af, bf);
            }
        }
        __syncthreads();   // done with Ks/Vs/Ps before next tile
    }

    // epilogue
    const float inv0 = 1.0f / l0;
    const float inv1 = 1.0f / l1;
    const size_t row0 = base + (size_t)(qt * 64 + qrow) * DMODEL;
    const size_t row1 = base + (size_t)(qt * 64 + qrow + 8) * DMODEL;
#pragma unroll
    for (int dt = 0; dt < 8; dt++) {
        const int c0 = dt * 8 + 2 * th;
        *(float2*)(ctx + row0 + c0) = make_float2(o[dt][0] * inv0, o[dt][1] * inv0);
        *(float2*)(ctx + row1 + c0) = make_float2(o[dt][2] * inv1, o[dt][3] * inv1);
    }
}

// ---------------------------------------------------------------------------
// out = LayerNorm(a + b) * gamma + beta, row-wise over DMODEL=1024.
// ---------------------------------------------------------------------------
__global__ __launch_bounds__(256)
void add_ln_kernel(const float* __restrict__ a, const float* __restrict__ b,
                   const float* __restrict__ gamma, const float* __restrict__ beta,
                   float* __restrict__ out) {
    const int row = blockIdx.x;
    const int tid = threadIdx.x;
    const size_t off = (size_t)row * DMODEL;

    __shared__ float r1[8], r2[8];

    float vals[4];
    float sum = 0.f, sq = 0.f;
#pragma unroll
    for (int t = 0; t < 4; t++) {
        int c = tid + t * 256;
        float vv = a[off + c] + b[off + c];
        vals[t] = vv;
        sum += vv;
        sq  += vv * vv;
    }
#pragma unroll
    for (int o = 16; o > 0; o >>= 1) {
        sum += __shfl_xor_sync(0xffffffffu, sum, o);
        sq  += __shfl_xor_sync(0xffffffffu, sq,  o);
    }
    const int wid = tid >> 5;
    if ((tid & 31) == 0) { r1[wid] = sum; r2[wid] = sq; }
    __syncthreads();
    float tot1 = 0.f, tot2 = 0.f;
#pragma unroll
    for (int w = 0; w < 8; w++) { tot1 += r1[w]; tot2 += r2[w]; }

    const float mu   = tot1 * (1.0f / DMODEL);
    const float var  = tot2 * (1.0f / DMODEL) - mu * mu;
    const float rstd = rsqrtf(var + LN_EPS);

#pragma unroll
    for (int t = 0; t < 4; t++) {
        int c = tid + t * 256;
        out[off + c] = (vals[t] - mu) * rstd * gamma[c] + beta[c];
    }
}

// ---------------------------------------------------------------------------
// Launcher
// ---------------------------------------------------------------------------
extern "C" void kernel_launch(void* const* d_in, const int* in_sizes, int n_in,
                              void* d_out, int out_size) {
    (void)in_sizes; (void)n_in; (void)out_size;
    const float* x   = (const float*)d_in[0];
    const float* wq  = (const float*)d_in[1];
    const float* wk  = (const float*)d_in[2];
    const float* wv  = (const float*)d_in[3];
    const float* wo  = (const float*)d_in[4];
    const float* w1  = (const float*)d_in[5];
    const float* b1  = (const float*)d_in[6];
    const float* w2  = (const float*)d_in[7];
    const float* b2  = (const float*)d_in[8];
    const float* g1  = (const float*)d_in[9];
    const float* be1 = (const float*)d_in[10];
    const float* g2  = (const float*)d_in[11];
    const float* be2 = (const float*)d_in[12];
    float* out = (float*)d_out;

    float *q, *k, *v, *ctx, *attn, *h, *ff, *f2;
    cudaGetSymbolAddress((void**)&q,    g_q);
    cudaGetSymbolAddress((void**)&k,    g_k);
    cudaGetSymbolAddress((void**)&v,    g_v);
    cudaGetSymbolAddress((void**)&ctx,  g_ctx);
    cudaGetSymbolAddress((void**)&attn, g_attn);
    cudaGetSymbolAddress((void**)&h,    g_h);
    cudaGetSymbolAddress((void**)&ff,   g_ff);
    cudaGetSymbolAddress((void**)&f2,   g_f2);

    cudaFuncSetAttribute(tf32_gemm<false, false>,
                         cudaFuncAttributeMaxDynamicSharedMemorySize, GEMM_SMEM);
    cudaFuncSetAttribute(tf32_gemm<true, true>,
                         cudaFuncAttributeMaxDynamicSharedMemorySize, GEMM_SMEM);
    cudaFuncSetAttribute(tf32_gemm<true, false>,
                         cudaFuncAttributeMaxDynamicSharedMemorySize, GEMM_SMEM);
    cudaFuncSetAttribute(flash_attn_tf32,
                         cudaFuncAttributeMaxDynamicSharedMemorySize, AT_SMEM);

    const dim3 g_dd(DMODEL / 128, NTOK / 128);   // (8, 64)
    const dim3 g_df(DFF / 128,    NTOK / 128);   // (32, 64)

    // Q, K, V projections
    tf32_gemm<false, false><<<g_dd, 256, GEMM_SMEM>>>(x, wq, nullptr, q, NTOK, DMODEL, DMODEL);
    tf32_gemm<false, false><<<g_dd, 256, GEMM_SMEM>>>(x, wk, nullptr, k, NTOK, DMODEL, DMODEL);
    tf32_gemm<false, false><<<g_dd, 256, GEMM_SMEM>>>(x, wv, nullptr, v, NTOK, DMODEL, DMODEL);

    // attention
    flash_attn_tf32<<<dim3(SEQ / 64, NHEAD, BATCH), 128, AT_SMEM>>>(q, k, v, ctx);

    // output projection
    tf32_gemm<false, false><<<g_dd, 256, GEMM_SMEM>>>(ctx, wo, nullptr, attn, NTOK, DMODEL, DMODEL);

    // add & norm 1
    add_ln_kernel<<<NTOK, 256>>>(x, attn, g1, be1, h);

    // FFN
    tf32_gemm<true, true ><<<g_df, 256, GEMM_SMEM>>>(h,  w1, b1, ff, NTOK, DFF,    DMODEL);
    tf32_gemm<true, false><<<g_dd, 256, GEMM_SMEM>>>(ff, w2, b2, f2, NTOK, DMODEL, DFF);

    // add & norm 2
    add_ln_kernel<<<NTOK, 256>>>(h, f2, g2, be2, out);
}